// round 3
// baseline (speedup 1.0000x reference)
#include <cuda_runtime.h>

// ---------------------------------------------------------------------------
// Problem constants
// ---------------------------------------------------------------------------
#define T0 4096
#define T1 8192
#define BATCH 8
#define KSZ 15
#define PADSZ 7
#define NJ 27

// Scratch (device globals; allocation is forbidden)
__device__ float g_bufA[BATCH * 270 * T1];
__device__ float g_bufB[BATCH * 270 * T1];
__device__ float g_gi[BATCH * 162 * T1];

// ---------------------------------------------------------------------------
// Skeleton adjacency (output joint -> input joints)
// ---------------------------------------------------------------------------
__constant__ int c_nb_cnt[NJ] = {
    8, 7, 6, 5, 4, 7, 6, 5, 4, 7, 8, 9, 6, 3, 7, 5, 4, 3, 7, 5, 4, 3, 6, 5, 6, 5, 12
};
__constant__ int c_nb[NJ][12] = {
    {0, 1, 2, 5, 6, 9, 10, 26, 0, 0, 0, 0},
    {0, 1, 2, 3, 5, 9, 26, 0, 0, 0, 0, 0},
    {0, 1, 2, 3, 4, 26, 0, 0, 0, 0, 0, 0},
    {1, 2, 3, 4, 22, 0, 0, 0, 0, 0, 0, 0},
    {2, 3, 4, 23, 0, 0, 0, 0, 0, 0, 0, 0},
    {0, 1, 5, 6, 7, 9, 26, 0, 0, 0, 0, 0},
    {0, 5, 6, 7, 8, 26, 0, 0, 0, 0, 0, 0},
    {5, 6, 7, 8, 24, 0, 0, 0, 0, 0, 0, 0},
    {6, 7, 8, 25, 0, 0, 0, 0, 0, 0, 0, 0},
    {0, 1, 5, 9, 10, 11, 26, 0, 0, 0, 0, 0},
    {0, 9, 10, 11, 12, 14, 18, 26, 0, 0, 0, 0},
    {9, 10, 11, 12, 13, 14, 15, 18, 19, 0, 0, 0},
    {10, 11, 12, 13, 14, 18, 0, 0, 0, 0, 0, 0},
    {11, 12, 13, 0, 0, 0, 0, 0, 0, 0, 0, 0},
    {10, 11, 12, 14, 15, 16, 18, 0, 0, 0, 0, 0},
    {11, 14, 15, 16, 17, 0, 0, 0, 0, 0, 0, 0},
    {14, 15, 16, 17, 0, 0, 0, 0, 0, 0, 0, 0},
    {15, 16, 17, 0, 0, 0, 0, 0, 0, 0, 0, 0},
    {10, 11, 12, 14, 18, 19, 20, 0, 0, 0, 0, 0},
    {11, 18, 19, 20, 21, 0, 0, 0, 0, 0, 0, 0},
    {18, 19, 20, 21, 0, 0, 0, 0, 0, 0, 0, 0},
    {19, 20, 21, 0, 0, 0, 0, 0, 0, 0, 0, 0},
    {1, 2, 3, 4, 22, 26, 0, 0, 0, 0, 0, 0},
    {2, 3, 4, 23, 26, 0, 0, 0, 0, 0, 0, 0},
    {5, 6, 7, 8, 24, 26, 0, 0, 0, 0, 0, 0},
    {6, 7, 8, 25, 26, 0, 0, 0, 0, 0, 0, 0},
    {0, 1, 2, 5, 6, 9, 10, 22, 23, 24, 25, 26}
};

// ---------------------------------------------------------------------------
// Skeleton conv kernel with register-prefetch double buffering.
//   grid  = (T/512, 27, BATCH), block = (32, CO_PJ)
//   Each thread: 16 timesteps x 1 output channel.
//   While computing neighbor tile ji from smem buffer buf, the next tile is
//   prefetched from gmem into registers, then stored to buf^1. ONE sync/iter.
// ---------------------------------------------------------------------------
template <int CI_PJ, int CO_PJ, bool ADD_IN, bool ADD_RES, bool LRELU>
__global__ void __launch_bounds__(32 * CO_PJ, 2)
sconv_kernel(const float* __restrict__ x,
             const float* __restrict__ x2,   // added to x if ADD_IN
             const float* __restrict__ w,
             const float* __restrict__ bias,
             const float* __restrict__ res,  // added to out if ADD_RES
             float* __restrict__ y,
             int T)
{
    constexpr int CIN  = CI_PJ * NJ;
    constexpr int COUT = CO_PJ * NJ;
    constexpr int TT   = 512;
    constexpr int TPT  = 16;
    constexpr int LROW = TT + 2 * PADSZ;          // 526 logical floats per ci row
    constexpr int PROW = 592;                     // padded physical row
    constexpr int NT   = 32 * CO_PJ;
    constexpr int NXS  = (CI_PJ * LROW + NT - 1) / NT;
    constexpr int NWS  = (CO_PJ * CI_PJ * KSZ + NT - 1) / NT;
    constexpr int XFL  = CI_PJ * PROW;            // floats per x buffer
    constexpr int WFL  = CO_PJ * CI_PJ * 16;      // floats per w buffer

    extern __shared__ __align__(16) float smf[];
    float* sxb0 = smf;              // [2][XFL]
    float* swb0 = smf + 2 * XFL;    // [2][WFL]

    const int b   = blockIdx.z;
    const int j   = blockIdx.y;
    const int t0  = blockIdx.x * TT;
    const int tx  = threadIdx.x;
    const int col = threadIdx.y;
    const int tid = col * 32 + tx;
    const int t_local = tx * TPT;

    float acc[TPT];
#pragma unroll
    for (int i = 0; i < TPT; ++i) acc[i] = 0.0f;

    float xr[NXS];
    float wr[NWS];

    // ---- prefetch into registers for one neighbor tile ----
    auto load_tile = [&](int jn) {
        const float* xb_  = x + ((size_t)b * CIN + jn * CI_PJ) * (size_t)T;
        const float* x2b_ = ADD_IN
            ? x2 + ((size_t)b * CIN + jn * CI_PJ) * (size_t)T : nullptr;
#pragma unroll
        for (int s = 0; s < NXS; ++s) {
            int idx = tid + s * NT;
            if (NXS * NT == CI_PJ * LROW || idx < CI_PJ * LROW) {
                int ci = idx / LROW;
                int p  = idx - ci * LROW;
                int g  = t0 - PADSZ + p;
                g = (g < 0) ? -g : (g >= T ? 2 * T - 2 - g : g);
                float v = __ldg(xb_ + ci * T + g);
                if (ADD_IN) v += __ldg(x2b_ + ci * T + g);
                xr[s] = v;
            }
        }
        const float* wb_ = w + ((size_t)(j * CO_PJ) * CIN + jn * CI_PJ) * KSZ;
#pragma unroll
        for (int s = 0; s < NWS; ++s) {
            int idx = tid + s * NT;
            if (NWS * NT == CO_PJ * CI_PJ * KSZ || idx < CO_PJ * CI_PJ * KSZ) {
                int co = idx / (CI_PJ * KSZ);
                int r  = idx - co * CI_PJ * KSZ;
                int ci = r / KSZ;
                int k  = r - ci * KSZ;
                wr[s] = __ldg(wb_ + ((size_t)co * CIN + ci) * KSZ + k);
            }
        }
    };

    // ---- store prefetched registers into smem buffer ----
    auto store_tile = [&](int buf) {
        float* sx = sxb0 + buf * XFL;
        float* sw = swb0 + buf * WFL;
#pragma unroll
        for (int s = 0; s < NXS; ++s) {
            int idx = tid + s * NT;
            if (NXS * NT == CI_PJ * LROW || idx < CI_PJ * LROW) {
                int ci = idx / LROW;
                int p  = idx - ci * LROW;
                sx[ci * PROW + p + 4 * (p >> 5)] = xr[s];
            }
        }
#pragma unroll
        for (int s = 0; s < NWS; ++s) {
            int idx = tid + s * NT;
            if (NWS * NT == CO_PJ * CI_PJ * KSZ || idx < CO_PJ * CI_PJ * KSZ) {
                int co = idx / (CI_PJ * KSZ);
                int r  = idx - co * CI_PJ * KSZ;
                int ci = r / KSZ;
                int k  = r - ci * KSZ;
                sw[(co * CI_PJ + ci) * 16 + k] = wr[s];
            }
        }
    };

    // ---- main pipelined loop over neighbor joints ----
    const int cnt = c_nb_cnt[j];
    load_tile(c_nb[j][0]);
    store_tile(0);
    __syncthreads();

    int buf = 0;
    for (int ji = 0; ji < cnt; ++ji) {
        const bool more = (ji + 1) < cnt;
        if (more) load_tile(c_nb[j][ji + 1]);   // gmem latency overlaps compute

        // ---- compute from smem buffer `buf` ----
        {
            const float* sx = sxb0 + buf * XFL;
            const float* sw = swb0 + buf * WFL;
#pragma unroll
            for (int ci = 0; ci < CI_PJ; ++ci) {
                float wv[16];
                {
                    const float4* wp = (const float4*)&sw[(col * CI_PJ + ci) * 16];
#pragma unroll
                    for (int q = 0; q < 4; ++q) ((float4*)wv)[q] = wp[q];
                }
                float xv[32];
                {
                    const float* xrow = &sx[ci * PROW];
#pragma unroll
                    for (int c = 0; c < 8; ++c) {
                        int lg = t_local + 4 * c;
                        int ph = lg + 4 * (lg >> 5);
                        ((float4*)xv)[c] = *(const float4*)(xrow + ph);
                    }
                }
#pragma unroll
                for (int tt = 0; tt < TPT; ++tt) {
#pragma unroll
                    for (int k = 0; k < KSZ; ++k) {
                        acc[tt] = fmaf(wv[k], xv[tt + k], acc[tt]);
                    }
                }
            }
        }

        if (more) store_tile(buf ^ 1);
        __syncthreads();
        buf ^= 1;
    }

    // ---- epilogue: bias, LeakyReLU, residual, store ----
    const int cg = j * CO_PJ + col;
    const float bv = bias[cg];
    float outv[TPT];
#pragma unroll
    for (int tt = 0; tt < TPT; ++tt) {
        float v = acc[tt] + bv;
        if (LRELU) v = (v > 0.0f) ? v : 0.2f * v;
        outv[tt] = v;
    }
    const size_t obase = ((size_t)b * COUT + cg) * (size_t)T + t0 + t_local;
    if (ADD_RES) {
#pragma unroll
        for (int q = 0; q < 4; ++q) {
            float4 r4 = *(const float4*)(res + obase + 4 * q);
            outv[4 * q + 0] += r4.x;
            outv[4 * q + 1] += r4.y;
            outv[4 * q + 2] += r4.z;
            outv[4 * q + 3] += r4.w;
        }
    }
#pragma unroll
    for (int q = 0; q < 4; ++q) {
        *(float4*)(y + obase + 4 * q) =
            make_float4(outv[4 * q + 0], outv[4 * q + 1], outv[4 * q + 2], outv[4 * q + 3]);
    }
}

// ---------------------------------------------------------------------------
// Linear interpolation (align_corners=False)
// ---------------------------------------------------------------------------
__global__ void interp_kernel(const float* __restrict__ in, float* __restrict__ out,
                              int Tin, int Tout, int BC)
{
    int idx = blockIdx.x * blockDim.x + threadIdx.x;
    if (idx >= BC * Tout) return;
    int t  = idx % Tout;
    int bc = idx / Tout;
    float src = ((float)t + 0.5f) * ((float)Tin / (float)Tout) - 0.5f;
    src = fminf(fmaxf(src, 0.0f), (float)(Tin - 1));
    int i0 = (int)floorf(src);
    int i1 = min(i0 + 1, Tin - 1);
    float wgt = src - (float)i0;
    const float* row = in + (size_t)bc * Tin;
    out[idx] = row[i0] * (1.0f - wgt) + row[i1] * wgt;
}

// ---------------------------------------------------------------------------
// Launch
// ---------------------------------------------------------------------------
static inline size_t smem_bytes(int ci_pj, int co_pj) {
    return 2u * ((size_t)ci_pj * 592 + (size_t)co_pj * ci_pj * 16) * 4u;
}

extern "C" void kernel_launch(void* const* d_in, const int* in_sizes, int n_in,
                              void* d_out, int out_size)
{
    (void)in_sizes; (void)n_in; (void)out_size;

    const float* noise0    = (const float*)d_in[0];
    const float* generated = (const float*)d_in[1];
    const float* noise1    = (const float*)d_in[2];

    const float* W[2][4];
    const float* Bv[2][4];
    int idx = 3;
    for (int s = 0; s < 2; ++s)
        for (int l = 0; l < 4; ++l) {
            W[s][l]  = (const float*)d_in[idx++];
            Bv[s][l] = (const float*)d_in[idx++];
        }

    float *bufA, *bufB, *gi;
    cudaGetSymbolAddress((void**)&bufA, g_bufA);
    cudaGetSymbolAddress((void**)&bufB, g_bufB);
    cudaGetSymbolAddress((void**)&gi, g_gi);

    float* g0 = (float*)d_out;
    float* g1 = g0 + (size_t)BATCH * 162 * T0;

    const size_t sm0 = smem_bytes(6, 5);
    const size_t sm1 = smem_bytes(5, 10);
    const size_t sm2 = smem_bytes(10, 10);
    const size_t sm3 = smem_bytes(10, 6);

    cudaFuncSetAttribute(sconv_kernel<6, 5, true, false, true>,
                         cudaFuncAttributeMaxDynamicSharedMemorySize, (int)sm0);
    cudaFuncSetAttribute(sconv_kernel<5, 10, false, false, true>,
                         cudaFuncAttributeMaxDynamicSharedMemorySize, (int)sm1);
    cudaFuncSetAttribute(sconv_kernel<10, 10, false, false, true>,
                         cudaFuncAttributeMaxDynamicSharedMemorySize, (int)sm2);
    cudaFuncSetAttribute(sconv_kernel<10, 6, false, true, false>,
                         cudaFuncAttributeMaxDynamicSharedMemorySize, (int)sm3);

    // ---------------- stage 0 (T = 4096) ----------------
    {
        dim3 grid(T0 / 512, NJ, BATCH);
        sconv_kernel<6, 5, true, false, true><<<grid, dim3(32, 5), sm0>>>(
            generated, noise0, W[0][0], Bv[0][0], nullptr, bufA, T0);
        sconv_kernel<5, 10, false, false, true><<<grid, dim3(32, 10), sm1>>>(
            bufA, nullptr, W[0][1], Bv[0][1], nullptr, bufB, T0);
        sconv_kernel<10, 10, false, false, true><<<grid, dim3(32, 10), sm2>>>(
            bufB, nullptr, W[0][2], Bv[0][2], nullptr, bufA, T0);
        sconv_kernel<10, 6, false, true, false><<<grid, dim3(32, 6), sm3>>>(
            bufA, nullptr, W[0][3], Bv[0][3], generated, g0, T0);
    }

    // ---------------- upsample g0 -> gi ----------------
    {
        int n = BATCH * 162 * T1;
        interp_kernel<<<(n + 255) / 256, 256>>>(g0, gi, T0, T1, BATCH * 162);
    }

    // ---------------- stage 1 (T = 8192) ----------------
    {
        dim3 grid(T1 / 512, NJ, BATCH);
        sconv_kernel<6, 5, true, false, true><<<grid, dim3(32, 5), sm0>>>(
            gi, noise1, W[1][0], Bv[1][0], nullptr, bufA, T1);
        sconv_kernel<5, 10, false, false, true><<<grid, dim3(32, 10), sm1>>>(
            bufA, nullptr, W[1][1], Bv[1][1], nullptr, bufB, T1);
        sconv_kernel<10, 10, false, false, true><<<grid, dim3(32, 10), sm2>>>(
            bufB, nullptr, W[1][2], Bv[1][2], nullptr, bufA, T1);
        sconv_kernel<10, 6, false, true, false><<<grid, dim3(32, 6), sm3>>>(
            bufA, nullptr, W[1][3], Bv[1][3], gi, g1, T1);
    }
}

// round 4
// speedup vs baseline: 1.3061x; 1.3061x over previous
#include <cuda_runtime.h>
#include <cstdint>

// ---------------------------------------------------------------------------
// Problem constants
// ---------------------------------------------------------------------------
#define T0 4096
#define T1 8192
#define BATCH 8
#define KSZ 15
#define PADSZ 7
#define NJ 27

// Scratch (device globals; allocation is forbidden)
__device__ float g_bufA[BATCH * 270 * T1];
__device__ float g_bufB[BATCH * 270 * T1];
__device__ float g_gi[BATCH * 162 * T1];

// ---------------------------------------------------------------------------
// Skeleton adjacency (output joint -> input joints)
// ---------------------------------------------------------------------------
__constant__ int c_nb_cnt[NJ] = {
    8, 7, 6, 5, 4, 7, 6, 5, 4, 7, 8, 9, 6, 3, 7, 5, 4, 3, 7, 5, 4, 3, 6, 5, 6, 5, 12
};
__constant__ int c_nb[NJ][12] = {
    {0, 1, 2, 5, 6, 9, 10, 26, 0, 0, 0, 0},
    {0, 1, 2, 3, 5, 9, 26, 0, 0, 0, 0, 0},
    {0, 1, 2, 3, 4, 26, 0, 0, 0, 0, 0, 0},
    {1, 2, 3, 4, 22, 0, 0, 0, 0, 0, 0, 0},
    {2, 3, 4, 23, 0, 0, 0, 0, 0, 0, 0, 0},
    {0, 1, 5, 6, 7, 9, 26, 0, 0, 0, 0, 0},
    {0, 5, 6, 7, 8, 26, 0, 0, 0, 0, 0, 0},
    {5, 6, 7, 8, 24, 0, 0, 0, 0, 0, 0, 0},
    {6, 7, 8, 25, 0, 0, 0, 0, 0, 0, 0, 0},
    {0, 1, 5, 9, 10, 11, 26, 0, 0, 0, 0, 0},
    {0, 9, 10, 11, 12, 14, 18, 26, 0, 0, 0, 0},
    {9, 10, 11, 12, 13, 14, 15, 18, 19, 0, 0, 0},
    {10, 11, 12, 13, 14, 18, 0, 0, 0, 0, 0, 0},
    {11, 12, 13, 0, 0, 0, 0, 0, 0, 0, 0, 0},
    {10, 11, 12, 14, 15, 16, 18, 0, 0, 0, 0, 0},
    {11, 14, 15, 16, 17, 0, 0, 0, 0, 0, 0, 0},
    {14, 15, 16, 17, 0, 0, 0, 0, 0, 0, 0, 0},
    {15, 16, 17, 0, 0, 0, 0, 0, 0, 0, 0, 0},
    {10, 11, 12, 14, 18, 19, 20, 0, 0, 0, 0, 0},
    {11, 18, 19, 20, 21, 0, 0, 0, 0, 0, 0, 0},
    {18, 19, 20, 21, 0, 0, 0, 0, 0, 0, 0, 0},
    {19, 20, 21, 0, 0, 0, 0, 0, 0, 0, 0, 0},
    {1, 2, 3, 4, 22, 26, 0, 0, 0, 0, 0, 0},
    {2, 3, 4, 23, 26, 0, 0, 0, 0, 0, 0, 0},
    {5, 6, 7, 8, 24, 26, 0, 0, 0, 0, 0, 0},
    {6, 7, 8, 25, 26, 0, 0, 0, 0, 0, 0, 0},
    {0, 1, 2, 5, 6, 9, 10, 22, 23, 24, 25, 26}
};

// ---------------------------------------------------------------------------
// cp.async helpers
// ---------------------------------------------------------------------------
__device__ __forceinline__ void cp4(float* dst_smem, const float* src) {
    uint32_t d = (uint32_t)__cvta_generic_to_shared(dst_smem);
    asm volatile("cp.async.ca.shared.global [%0], [%1], 4;" :: "r"(d), "l"(src));
}
__device__ __forceinline__ void cp_commit() {
    asm volatile("cp.async.commit_group;" ::: "memory");
}
template <int N>
__device__ __forceinline__ void cp_wait() {
    asm volatile("cp.async.wait_group %0;" :: "n"(N) : "memory");
}

// ---------------------------------------------------------------------------
// Skeleton conv kernel.
//   grid  = (T/512, 27, BATCH), block = (32, CO_PJ)
//   Each thread: 16 timesteps x 1 output channel.
//   PIPE=true: cp.async double-buffered neighbor tiles (latency hidden).
//   PIPE=false (ADD_IN layers): synchronous staging, single buffer.
// ---------------------------------------------------------------------------
template <int CI_PJ, int CO_PJ, bool ADD_IN, bool ADD_RES, bool LRELU, bool PIPE>
__global__ void sconv_kernel(const float* __restrict__ x,
                             const float* __restrict__ x2,
                             const float* __restrict__ w,
                             const float* __restrict__ bias,
                             const float* __restrict__ res,
                             float* __restrict__ y,
                             int T)
{
    constexpr int CIN  = CI_PJ * NJ;
    constexpr int COUT = CO_PJ * NJ;
    constexpr int TT   = 512;
    constexpr int TPT  = 16;
    constexpr int LROW = TT + 2 * PADSZ;          // 526 logical floats per ci row
    constexpr int PROW = 592;                     // padded physical row
    constexpr int NT   = 32 * CO_PJ;
    constexpr int NSX  = (LROW + 31) / 32;        // 17 chunks per row
    constexpr int XFL  = CI_PJ * PROW;
    constexpr int WFL  = CO_PJ * CI_PJ * 16;
    constexpr int NWEL = CO_PJ * CI_PJ * KSZ;

    extern __shared__ __align__(16) float smf[];
    constexpr int NBUF = PIPE ? 2 : 1;
    float* sxb0 = smf;                  // [NBUF][XFL]
    float* swb0 = smf + NBUF * XFL;     // [NBUF][WFL]

    const int b   = blockIdx.z;
    const int j   = blockIdx.y;
    const int t0  = blockIdx.x * TT;
    const int tx  = threadIdx.x;
    const int col = threadIdx.y;        // also warp id within block
    const int tid = col * 32 + tx;
    const int t_local = tx * TPT;

    float acc[TPT];
#pragma unroll
    for (int i = 0; i < TPT; ++i) acc[i] = 0.0f;

    const int cnt = c_nb_cnt[j];

    // ---- async staging of one neighbor tile into buffer bb (PIPE path) ----
    auto stage_async = [&](int bb, int jn) {
        float* sx = sxb0 + bb * XFL;
        float* sw = swb0 + bb * WFL;
        const float* xb_ = x + ((size_t)b * CIN + jn * CI_PJ) * (size_t)T;
        for (int ci = col; ci < CI_PJ; ci += CO_PJ) {
            const float* src = xb_ + (size_t)ci * T;
            float* drow = sx + ci * PROW + tx;
#pragma unroll
            for (int s = 0; s < NSX; ++s) {
                int p = tx + 32 * s;
                if (p < LROW) {
                    int g = t0 - PADSZ + p;
                    g = (g < 0) ? -g : (g >= T ? 2 * T - 2 - g : g);
                    cp4(drow + 36 * s, src + g);
                }
            }
        }
        const float* wb_ = w + ((size_t)(j * CO_PJ) * CIN + jn * CI_PJ) * KSZ;
        for (int idx = tid; idx < NWEL; idx += NT) {
            int r  = idx / KSZ;
            int k  = idx - r * KSZ;
            int co = r / CI_PJ;
            int ci = r - co * CI_PJ;
            cp4(&sw[r * 16 + k], wb_ + ((size_t)co * CIN + ci) * KSZ + k);
        }
    };

    // ---- synchronous staging (ADD_IN path) ----
    auto stage_sync = [&](int jn) {
        const float* xa_ = x  + ((size_t)b * CIN + jn * CI_PJ) * (size_t)T;
        const float* xc_ = x2 + ((size_t)b * CIN + jn * CI_PJ) * (size_t)T;
        for (int ci = col; ci < CI_PJ; ci += CO_PJ) {
            const float* sa = xa_ + (size_t)ci * T;
            const float* sc = xc_ + (size_t)ci * T;
            float* drow = sxb0 + ci * PROW + tx;
#pragma unroll
            for (int s = 0; s < NSX; ++s) {
                int p = tx + 32 * s;
                if (p < LROW) {
                    int g = t0 - PADSZ + p;
                    g = (g < 0) ? -g : (g >= T ? 2 * T - 2 - g : g);
                    drow[36 * s] = __ldg(sa + g) + __ldg(sc + g);
                }
            }
        }
        const float* wb_ = w + ((size_t)(j * CO_PJ) * CIN + jn * CI_PJ) * KSZ;
        for (int idx = tid; idx < NWEL; idx += NT) {
            int r  = idx / KSZ;
            int k  = idx - r * KSZ;
            int co = r / CI_PJ;
            int ci = r - co * CI_PJ;
            swb0[r * 16 + k] = __ldg(wb_ + ((size_t)co * CIN + ci) * KSZ + k);
        }
    };

    // ---- compute one staged tile (identical structure to R1) ----
    auto compute = [&](int bb) {
        const float* sx = sxb0 + bb * XFL;
        const float* sw = swb0 + bb * WFL;
#pragma unroll
        for (int ci = 0; ci < CI_PJ; ++ci) {
            float wv[16];
            {
                const float4* wp = (const float4*)&sw[(col * CI_PJ + ci) * 16];
#pragma unroll
                for (int q = 0; q < 4; ++q) ((float4*)wv)[q] = wp[q];
            }
            float xv[32];
            {
                const float* xrow = &sx[ci * PROW];
#pragma unroll
                for (int c = 0; c < 8; ++c) {
                    int lg = t_local + 4 * c;
                    int ph = lg + 4 * (lg >> 5);
                    ((float4*)xv)[c] = *(const float4*)(xrow + ph);
                }
            }
#pragma unroll
            for (int tt = 0; tt < TPT; ++tt) {
#pragma unroll
                for (int k = 0; k < KSZ; ++k) {
                    acc[tt] = fmaf(wv[k], xv[tt + k], acc[tt]);
                }
            }
        }
    };

    if (PIPE) {
        stage_async(0, c_nb[j][0]);
        cp_commit();
        int buf = 0;
        for (int ji = 0; ji < cnt; ++ji) {
            __syncthreads();            // prior compute done: safe to overwrite buf^1
            if (ji + 1 < cnt) {
                stage_async(buf ^ 1, c_nb[j][ji + 1]);
                cp_commit();
                cp_wait<1>();           // tile ji complete
            } else {
                cp_wait<0>();
            }
            __syncthreads();
            compute(buf);
            buf ^= 1;
        }
    } else {
        for (int ji = 0; ji < cnt; ++ji) {
            __syncthreads();
            stage_sync(c_nb[j][ji]);
            __syncthreads();
            compute(0);
        }
    }

    // ---- epilogue: bias, LeakyReLU, residual, store ----
    const int cg = j * CO_PJ + col;
    const float bv = bias[cg];
    float outv[TPT];
#pragma unroll
    for (int tt = 0; tt < TPT; ++tt) {
        float v = acc[tt] + bv;
        if (LRELU) v = (v > 0.0f) ? v : 0.2f * v;
        outv[tt] = v;
    }
    const size_t obase = ((size_t)b * COUT + cg) * (size_t)T + t0 + t_local;
    if (ADD_RES) {
#pragma unroll
        for (int q = 0; q < 4; ++q) {
            float4 r4 = *(const float4*)(res + obase + 4 * q);
            outv[4 * q + 0] += r4.x;
            outv[4 * q + 1] += r4.y;
            outv[4 * q + 2] += r4.z;
            outv[4 * q + 3] += r4.w;
        }
    }
#pragma unroll
    for (int q = 0; q < 4; ++q) {
        *(float4*)(y + obase + 4 * q) =
            make_float4(outv[4 * q + 0], outv[4 * q + 1], outv[4 * q + 2], outv[4 * q + 3]);
    }
}

// ---------------------------------------------------------------------------
// Linear interpolation (align_corners=False)
// ---------------------------------------------------------------------------
__global__ void interp_kernel(const float* __restrict__ in, float* __restrict__ out,
                              int Tin, int Tout, int BC)
{
    int idx = blockIdx.x * blockDim.x + threadIdx.x;
    if (idx >= BC * Tout) return;
    int t  = idx % Tout;
    int bc = idx / Tout;
    float src = ((float)t + 0.5f) * ((float)Tin / (float)Tout) - 0.5f;
    src = fminf(fmaxf(src, 0.0f), (float)(Tin - 1));
    int i0 = (int)floorf(src);
    int i1 = min(i0 + 1, Tin - 1);
    float wgt = src - (float)i0;
    const float* row = in + (size_t)bc * Tin;
    out[idx] = row[i0] * (1.0f - wgt) + row[i1] * wgt;
}

// ---------------------------------------------------------------------------
// Launch
// ---------------------------------------------------------------------------
static inline size_t smem_bytes(int ci_pj, int co_pj, int nbuf) {
    return (size_t)nbuf * ((size_t)ci_pj * 592 + (size_t)co_pj * ci_pj * 16) * 4u;
}

extern "C" void kernel_launch(void* const* d_in, const int* in_sizes, int n_in,
                              void* d_out, int out_size)
{
    (void)in_sizes; (void)n_in; (void)out_size;

    const float* noise0    = (const float*)d_in[0];
    const float* generated = (const float*)d_in[1];
    const float* noise1    = (const float*)d_in[2];

    const float* W[2][4];
    const float* Bv[2][4];
    int idx = 3;
    for (int s = 0; s < 2; ++s)
        for (int l = 0; l < 4; ++l) {
            W[s][l]  = (const float*)d_in[idx++];
            Bv[s][l] = (const float*)d_in[idx++];
        }

    float *bufA, *bufB, *gi;
    cudaGetSymbolAddress((void**)&bufA, g_bufA);
    cudaGetSymbolAddress((void**)&bufB, g_bufB);
    cudaGetSymbolAddress((void**)&gi, g_gi);

    float* g0 = (float*)d_out;
    float* g1 = g0 + (size_t)BATCH * 162 * T0;

    const size_t sm0 = smem_bytes(6, 5, 1);     // L0: ADD_IN, single buffer
    const size_t sm1 = smem_bytes(5, 10, 2);    // L1: piped
    const size_t sm2 = smem_bytes(10, 10, 2);   // L2: piped
    const size_t sm3 = smem_bytes(10, 6, 2);    // L3: piped

    cudaFuncSetAttribute(sconv_kernel<6, 5, true, false, true, false>,
                         cudaFuncAttributeMaxDynamicSharedMemorySize, (int)sm0);
    cudaFuncSetAttribute(sconv_kernel<5, 10, false, false, true, true>,
                         cudaFuncAttributeMaxDynamicSharedMemorySize, (int)sm1);
    cudaFuncSetAttribute(sconv_kernel<10, 10, false, false, true, true>,
                         cudaFuncAttributeMaxDynamicSharedMemorySize, (int)sm2);
    cudaFuncSetAttribute(sconv_kernel<10, 6, false, true, false, true>,
                         cudaFuncAttributeMaxDynamicSharedMemorySize, (int)sm3);

    // ---------------- stage 0 (T = 4096) ----------------
    {
        dim3 grid(T0 / 512, NJ, BATCH);
        sconv_kernel<6, 5, true, false, true, false><<<grid, dim3(32, 5), sm0>>>(
            generated, noise0, W[0][0], Bv[0][0], nullptr, bufA, T0);
        sconv_kernel<5, 10, false, false, true, true><<<grid, dim3(32, 10), sm1>>>(
            bufA, nullptr, W[0][1], Bv[0][1], nullptr, bufB, T0);
        sconv_kernel<10, 10, false, false, true, true><<<grid, dim3(32, 10), sm2>>>(
            bufB, nullptr, W[0][2], Bv[0][2], nullptr, bufA, T0);
        sconv_kernel<10, 6, false, true, false, true><<<grid, dim3(32, 6), sm3>>>(
            bufA, nullptr, W[0][3], Bv[0][3], generated, g0, T0);
    }

    // ---------------- upsample g0 -> gi ----------------
    {
        int n = BATCH * 162 * T1;
        interp_kernel<<<(n + 255) / 256, 256>>>(g0, gi, T0, T1, BATCH * 162);
    }

    // ---------------- stage 1 (T = 8192) ----------------
    {
        dim3 grid(T1 / 512, NJ, BATCH);
        sconv_kernel<6, 5, true, false, true, false><<<grid, dim3(32, 5), sm0>>>(
            gi, noise1, W[1][0], Bv[1][0], nullptr, bufA, T1);
        sconv_kernel<5, 10, false, false, true, true><<<grid, dim3(32, 10), sm1>>>(
            bufA, nullptr, W[1][1], Bv[1][1], nullptr, bufB, T1);
        sconv_kernel<10, 10, false, false, true, true><<<grid, dim3(32, 10), sm2>>>(
            bufB, nullptr, W[1][2], Bv[1][2], nullptr, bufA, T1);
        sconv_kernel<10, 6, false, true, false, true><<<grid, dim3(32, 6), sm3>>>(
            bufA, nullptr, W[1][3], Bv[1][3], gi, g1, T1);
    }
}

// round 5
// speedup vs baseline: 1.4854x; 1.1373x over previous
#include <cuda_runtime.h>
#include <cstdint>

// ---------------------------------------------------------------------------
// Problem constants
// ---------------------------------------------------------------------------
#define T0 4096
#define T1 8192
#define BATCH 8
#define KSZ 15
#define PADSZ 7
#define NJ 27

// Scratch (device globals; allocation is forbidden)
__device__ float g_bufA[BATCH * 270 * T1];
__device__ float g_bufB[BATCH * 270 * T1];
__device__ float g_bufC[BATCH * 162 * T1];   // pre-summed input (x + noise)
__device__ float g_gi[BATCH * 162 * T1];

// ---------------------------------------------------------------------------
// Skeleton adjacency (output joint -> input joints)
// ---------------------------------------------------------------------------
__constant__ int c_nb_cnt[NJ] = {
    8, 7, 6, 5, 4, 7, 6, 5, 4, 7, 8, 9, 6, 3, 7, 5, 4, 3, 7, 5, 4, 3, 6, 5, 6, 5, 12
};
__constant__ int c_nb[NJ][12] = {
    {0, 1, 2, 5, 6, 9, 10, 26, 0, 0, 0, 0},
    {0, 1, 2, 3, 5, 9, 26, 0, 0, 0, 0, 0},
    {0, 1, 2, 3, 4, 26, 0, 0, 0, 0, 0, 0},
    {1, 2, 3, 4, 22, 0, 0, 0, 0, 0, 0, 0},
    {2, 3, 4, 23, 0, 0, 0, 0, 0, 0, 0, 0},
    {0, 1, 5, 6, 7, 9, 26, 0, 0, 0, 0, 0},
    {0, 5, 6, 7, 8, 26, 0, 0, 0, 0, 0, 0},
    {5, 6, 7, 8, 24, 0, 0, 0, 0, 0, 0, 0},
    {6, 7, 8, 25, 0, 0, 0, 0, 0, 0, 0, 0},
    {0, 1, 5, 9, 10, 11, 26, 0, 0, 0, 0, 0},
    {0, 9, 10, 11, 12, 14, 18, 26, 0, 0, 0, 0},
    {9, 10, 11, 12, 13, 14, 15, 18, 19, 0, 0, 0},
    {10, 11, 12, 13, 14, 18, 0, 0, 0, 0, 0, 0},
    {11, 12, 13, 0, 0, 0, 0, 0, 0, 0, 0, 0},
    {10, 11, 12, 14, 15, 16, 18, 0, 0, 0, 0, 0},
    {11, 14, 15, 16, 17, 0, 0, 0, 0, 0, 0, 0},
    {14, 15, 16, 17, 0, 0, 0, 0, 0, 0, 0, 0},
    {15, 16, 17, 0, 0, 0, 0, 0, 0, 0, 0, 0},
    {10, 11, 12, 14, 18, 19, 20, 0, 0, 0, 0, 0},
    {11, 18, 19, 20, 21, 0, 0, 0, 0, 0, 0, 0},
    {18, 19, 20, 21, 0, 0, 0, 0, 0, 0, 0, 0},
    {19, 20, 21, 0, 0, 0, 0, 0, 0, 0, 0, 0},
    {1, 2, 3, 4, 22, 26, 0, 0, 0, 0, 0, 0},
    {2, 3, 4, 23, 26, 0, 0, 0, 0, 0, 0, 0},
    {5, 6, 7, 8, 24, 26, 0, 0, 0, 0, 0, 0},
    {6, 7, 8, 25, 26, 0, 0, 0, 0, 0, 0, 0},
    {0, 1, 2, 5, 6, 9, 10, 22, 23, 24, 25, 26}
};

// ---------------------------------------------------------------------------
// cp.async helpers
// ---------------------------------------------------------------------------
__device__ __forceinline__ void cp4(float* dst_smem, const float* src) {
    uint32_t d = (uint32_t)__cvta_generic_to_shared(dst_smem);
    asm volatile("cp.async.ca.shared.global [%0], [%1], 4;" :: "r"(d), "l"(src));
}
__device__ __forceinline__ void cp_commit() {
    asm volatile("cp.async.commit_group;" ::: "memory");
}
template <int N>
__device__ __forceinline__ void cp_wait() {
    asm volatile("cp.async.wait_group %0;" :: "n"(N) : "memory");
}

// ---------------------------------------------------------------------------
// Skeleton conv kernel, cp.async double-buffered.
//   grid  = (T/256, 27, BATCH), block = (32, CO_PJ)
//   Each thread: 8 timesteps x 1 output channel.
// ---------------------------------------------------------------------------
template <int CI_PJ, int CO_PJ, bool ADD_RES, bool LRELU>
__global__ void sconv_kernel(const float* __restrict__ x,
                             const float* __restrict__ w,
                             const float* __restrict__ bias,
                             const float* __restrict__ res,
                             float* __restrict__ y,
                             int T)
{
    constexpr int CIN  = CI_PJ * NJ;
    constexpr int COUT = CO_PJ * NJ;
    constexpr int TT   = 256;
    constexpr int TPT  = 8;
    constexpr int LROW = TT + 2 * PADSZ;          // 270 logical floats per ci row
    constexpr int PROW = 304;                     // pad-4-per-32 physical row
    constexpr int NT   = 32 * CO_PJ;
    constexpr int NSX  = (LROW + 31) / 32;        // 9 chunks per row
    constexpr int XFL  = CI_PJ * PROW;
    constexpr int WFL  = CO_PJ * CI_PJ * 16;
    constexpr int NWEL = CO_PJ * CI_PJ * KSZ;

    extern __shared__ __align__(16) float smf[];
    float* sxb0 = smf;                  // [2][XFL]
    float* swb0 = smf + 2 * XFL;        // [2][WFL]

    const int b   = blockIdx.z;
    const int j   = blockIdx.y;
    const int t0  = blockIdx.x * TT;
    const int tx  = threadIdx.x;
    const int col = threadIdx.y;        // output channel within joint; warp id
    const int tid = col * 32 + tx;
    const int t_local = tx * TPT;

    float acc[TPT];
#pragma unroll
    for (int i = 0; i < TPT; ++i) acc[i] = 0.0f;

    const int cnt = c_nb_cnt[j];

    // ---- async staging of one neighbor tile into buffer bb ----
    auto stage_async = [&](int bb, int jn) {
        float* sx = sxb0 + bb * XFL;
        float* sw = swb0 + bb * WFL;
        const float* xb_ = x + ((size_t)b * CIN + jn * CI_PJ) * (size_t)T;
        for (int ci = col; ci < CI_PJ; ci += CO_PJ) {
            const float* src = xb_ + (size_t)ci * T;
            float* drow = sx + ci * PROW + tx;
#pragma unroll
            for (int s = 0; s < NSX; ++s) {
                int p = tx + 32 * s;
                if (p < LROW) {
                    int g = t0 - PADSZ + p;
                    g = (g < 0) ? -g : (g >= T ? 2 * T - 2 - g : g);
                    cp4(drow + 36 * s, src + g);
                }
            }
        }
        const float* wb_ = w + ((size_t)(j * CO_PJ) * CIN + jn * CI_PJ) * KSZ;
        for (int idx = tid; idx < NWEL; idx += NT) {
            int r  = idx / KSZ;
            int k  = idx - r * KSZ;
            int co = r / CI_PJ;
            int ci = r - co * CI_PJ;
            cp4(&sw[r * 16 + k], wb_ + ((size_t)co * CIN + ci) * KSZ + k);
        }
    };

    // ---- compute one staged tile ----
    auto compute = [&](int bb) {
        const float* sx = sxb0 + bb * XFL;
        const float* sw = swb0 + bb * WFL;
#pragma unroll
        for (int ci = 0; ci < CI_PJ; ++ci) {
            float wv[16];
            {
                const float4* wp = (const float4*)&sw[(col * CI_PJ + ci) * 16];
#pragma unroll
                for (int q = 0; q < 4; ++q) ((float4*)wv)[q] = wp[q];
            }
            float xv[24];                         // need TPT+14 = 22, load 24
            {
                const float* xrow = &sx[ci * PROW];
#pragma unroll
                for (int c = 0; c < 6; ++c) {
                    int lg = t_local + 4 * c;
                    int ph = lg + 4 * (lg >> 5);
                    ((float4*)xv)[c] = *(const float4*)(xrow + ph);
                }
            }
#pragma unroll
            for (int tt = 0; tt < TPT; ++tt) {
#pragma unroll
                for (int k = 0; k < KSZ; ++k) {
                    acc[tt] = fmaf(wv[k], xv[tt + k], acc[tt]);
                }
            }
        }
    };

    stage_async(0, c_nb[j][0]);
    cp_commit();
    int buf = 0;
    for (int ji = 0; ji < cnt; ++ji) {
        __syncthreads();                // prior compute done: safe to overwrite buf^1
        if (ji + 1 < cnt) {
            stage_async(buf ^ 1, c_nb[j][ji + 1]);
            cp_commit();
            cp_wait<1>();               // tile ji complete
        } else {
            cp_wait<0>();
        }
        __syncthreads();
        compute(buf);
        buf ^= 1;
    }

    // ---- epilogue: bias, LeakyReLU, residual, store ----
    const int cg = j * CO_PJ + col;
    const float bv = bias[cg];
    float outv[TPT];
#pragma unroll
    for (int tt = 0; tt < TPT; ++tt) {
        float v = acc[tt] + bv;
        if (LRELU) v = (v > 0.0f) ? v : 0.2f * v;
        outv[tt] = v;
    }
    const size_t obase = ((size_t)b * COUT + cg) * (size_t)T + t0 + t_local;
    if (ADD_RES) {
#pragma unroll
        for (int q = 0; q < 2; ++q) {
            float4 r4 = *(const float4*)(res + obase + 4 * q);
            outv[4 * q + 0] += r4.x;
            outv[4 * q + 1] += r4.y;
            outv[4 * q + 2] += r4.z;
            outv[4 * q + 3] += r4.w;
        }
    }
#pragma unroll
    for (int q = 0; q < 2; ++q) {
        *(float4*)(y + obase + 4 * q) =
            make_float4(outv[4 * q + 0], outv[4 * q + 1], outv[4 * q + 2], outv[4 * q + 3]);
    }
}

// ---------------------------------------------------------------------------
// Elementwise sum: out = a + b
// ---------------------------------------------------------------------------
__global__ void add_kernel(const float* __restrict__ a, const float* __restrict__ bsrc,
                           float* __restrict__ out, int n)
{
    int i = blockIdx.x * blockDim.x + threadIdx.x;
    int i4 = 4 * i;
    if (i4 + 3 < n) {
        float4 va = *(const float4*)(a + i4);
        float4 vb = *(const float4*)(bsrc + i4);
        *(float4*)(out + i4) = make_float4(va.x + vb.x, va.y + vb.y,
                                           va.z + vb.z, va.w + vb.w);
    }
}

// ---------------------------------------------------------------------------
// Linear interp (align_corners=False) fused with noise add:
//   gi = interp(in);  sum = gi + noise
// ---------------------------------------------------------------------------
__global__ void interp_add_kernel(const float* __restrict__ in,
                                  const float* __restrict__ noise,
                                  float* __restrict__ gi,
                                  float* __restrict__ sum,
                                  int Tin, int Tout, int BC)
{
    int idx = blockIdx.x * blockDim.x + threadIdx.x;
    if (idx >= BC * Tout) return;
    int t  = idx % Tout;
    int bc = idx / Tout;
    float src = ((float)t + 0.5f) * ((float)Tin / (float)Tout) - 0.5f;
    src = fminf(fmaxf(src, 0.0f), (float)(Tin - 1));
    int i0 = (int)floorf(src);
    int i1 = min(i0 + 1, Tin - 1);
    float wgt = src - (float)i0;
    const float* row = in + (size_t)bc * Tin;
    float v = row[i0] * (1.0f - wgt) + row[i1] * wgt;
    gi[idx]  = v;
    sum[idx] = v + noise[idx];
}

// ---------------------------------------------------------------------------
// Launch
// ---------------------------------------------------------------------------
static inline size_t smem_bytes(int ci_pj, int co_pj) {
    return 2u * ((size_t)ci_pj * 304 + (size_t)co_pj * ci_pj * 16) * 4u;
}

extern "C" void kernel_launch(void* const* d_in, const int* in_sizes, int n_in,
                              void* d_out, int out_size)
{
    (void)in_sizes; (void)n_in; (void)out_size;

    const float* noise0    = (const float*)d_in[0];
    const float* generated = (const float*)d_in[1];
    const float* noise1    = (const float*)d_in[2];

    const float* W[2][4];
    const float* Bv[2][4];
    int idx = 3;
    for (int s = 0; s < 2; ++s)
        for (int l = 0; l < 4; ++l) {
            W[s][l]  = (const float*)d_in[idx++];
            Bv[s][l] = (const float*)d_in[idx++];
        }

    float *bufA, *bufB, *bufC, *gi;
    cudaGetSymbolAddress((void**)&bufA, g_bufA);
    cudaGetSymbolAddress((void**)&bufB, g_bufB);
    cudaGetSymbolAddress((void**)&bufC, g_bufC);
    cudaGetSymbolAddress((void**)&gi, g_gi);

    float* g0 = (float*)d_out;
    float* g1 = g0 + (size_t)BATCH * 162 * T0;

    const size_t sm0 = smem_bytes(6, 5);
    const size_t sm1 = smem_bytes(5, 10);
    const size_t sm2 = smem_bytes(10, 10);
    const size_t sm3 = smem_bytes(10, 6);

    cudaFuncSetAttribute(sconv_kernel<6, 5, false, true>,
                         cudaFuncAttributeMaxDynamicSharedMemorySize, (int)sm0);
    cudaFuncSetAttribute(sconv_kernel<5, 10, false, true>,
                         cudaFuncAttributeMaxDynamicSharedMemorySize, (int)sm1);
    cudaFuncSetAttribute(sconv_kernel<10, 10, false, true>,
                         cudaFuncAttributeMaxDynamicSharedMemorySize, (int)sm2);
    cudaFuncSetAttribute(sconv_kernel<10, 6, true, false>,
                         cudaFuncAttributeMaxDynamicSharedMemorySize, (int)sm3);

    // ---------------- stage 0 (T = 4096) ----------------
    {
        int n0 = BATCH * 162 * T0;
        add_kernel<<<(n0 / 4 + 255) / 256, 256>>>(generated, noise0, bufC, n0);

        dim3 grid(T0 / 256, NJ, BATCH);
        sconv_kernel<6, 5, false, true><<<grid, dim3(32, 5), sm0>>>(
            bufC, W[0][0], Bv[0][0], nullptr, bufA, T0);
        sconv_kernel<5, 10, false, true><<<grid, dim3(32, 10), sm1>>>(
            bufA, W[0][1], Bv[0][1], nullptr, bufB, T0);
        sconv_kernel<10, 10, false, true><<<grid, dim3(32, 10), sm2>>>(
            bufB, W[0][2], Bv[0][2], nullptr, bufA, T0);
        sconv_kernel<10, 6, true, false><<<grid, dim3(32, 6), sm3>>>(
            bufA, W[0][3], Bv[0][3], generated, g0, T0);
    }

    // ---------------- upsample + noise add ----------------
    {
        int n = BATCH * 162 * T1;
        interp_add_kernel<<<(n + 255) / 256, 256>>>(g0, noise1, gi, bufC,
                                                    T0, T1, BATCH * 162);
    }

    // ---------------- stage 1 (T = 8192) ----------------
    {
        dim3 grid(T1 / 256, NJ, BATCH);
        sconv_kernel<6, 5, false, true><<<grid, dim3(32, 5), sm0>>>(
            bufC, W[1][0], Bv[1][0], nullptr, bufA, T1);
        sconv_kernel<5, 10, false, true><<<grid, dim3(32, 10), sm1>>>(
            bufA, W[1][1], Bv[1][1], nullptr, bufB, T1);
        sconv_kernel<10, 10, false, true><<<grid, dim3(32, 10), sm2>>>(
            bufB, W[1][2], Bv[1][2], nullptr, bufA, T1);
        sconv_kernel<10, 6, true, false><<<grid, dim3(32, 6), sm3>>>(
            bufA, W[1][3], Bv[1][3], gi, g1, T1);
    }
}